// round 1
// baseline (speedup 1.0000x reference)
#include <cuda_runtime.h>

// S4D selective-scan (non-stateful, eps-regularized) for B=2, L=2048, H=128, N=64.
// Strategy: the reference is a pointwise term computation + cumsum over t + dot over n.
//   term[b,t,h,n] = u[b,t,h] * dB[h,n] / (exp(dA[h,n]*t) + 1e-12)
//   x = cumsum_t(term) * exp(dA*t);  y = Re(sum_n x*C[n]);  out = y + u*D
// exp(dA*t) is recomputed directly per t (expf + sincosf on the SAME fp32-rounded
// arguments as the reference) to match the reference numerics, which are sensitive
// to the exact rounding of the angle Im(dA)*t (up to ~4e4 rad).
// Two kernels: K1 computes per-chunk complex sums of 'term' (both batches share the
// expensive b-independent exp/sincos/rcp). K3 rebuilds chunk offsets from the small
// (4MB, L2-resident) chunk-sum array, replays the chunk scan, and reduces over n.

#define BSZ     2
#define LSEQ    2048
#define NH      128
#define ND      64
#define CHUNK   64
#define NCHUNK  (LSEQ / CHUNK)
#define EPSV    1e-12f

// scratch: per-(b,h,chunk,n) complex chunk sums. 2*128*32*64 float2 = 4 MB.
__device__ float2 g_P[BSZ * NH * NCHUNK * ND];

struct SSMParams {
    float dAr, dAi;   // dA = Lam * step
    float dBr, dBi;   // dB = Bc * (exp(dA)-1) / Lam
    float Cr, Ci;     // C[n]
};

__device__ __forceinline__ SSMParams make_params(
    const float* __restrict__ log_A_real, const float* __restrict__ A_imag,
    const float* __restrict__ Bp, const float* __restrict__ log_dt,
    const float* __restrict__ Cp, int h, int n)
{
    int hn = h * ND + n;
    float LamR = -expf(log_A_real[hn]);
    float LamI = A_imag[hn];
    float step = expf(log_dt[0]);
    float dAr = LamR * step;
    float dAi = LamI * step;
    // exp(dA) - 1  (complex)
    float e = expf(dAr);
    float s, c;
    sincosf(dAi, &s, &c);
    float em1r = e * c - 1.0f;
    float em1i = e * s;
    // Bc * (exp(dA)-1)
    float Br = Bp[hn * 2 + 0], Bi = Bp[hn * 2 + 1];
    float numr = Br * em1r - Bi * em1i;
    float numi = Br * em1i + Bi * em1r;
    // / Lam
    float inv = 1.0f / (LamR * LamR + LamI * LamI);
    SSMParams p;
    p.dAr = dAr; p.dAi = dAi;
    p.dBr = (numr * LamR + numi * LamI) * inv;
    p.dBi = (numi * LamR - numr * LamI) * inv;
    p.Cr = Cp[n * 2 + 0];
    p.Ci = Cp[n * 2 + 1];
    return p;
}

// Per-timestep heavy part, b-independent:
// q = dB / (exp(dA*t) + eps)   (complex), plus v = exp(dA*t) returned.
__device__ __forceinline__ void step_qv(const SSMParams& P, int t,
                                        float& q1, float& q2,
                                        float& vr, float& vi)
{
    float tf = (float)t;
    float e = expf(P.dAr * tf);
    float sn, cs;
    sincosf(P.dAi * tf, &sn, &cs);
    vr = e * cs;
    vi = e * sn;
    float dc = vr + EPSV;           // eps added to real part only (matches reference)
    float dd = vi;
    float inv = 1.0f / (dc * dc + dd * dd);
    q1 = (P.dBr * dc + P.dBi * dd) * inv;
    q2 = (P.dBi * dc - P.dBr * dd) * inv;
}

__global__ __launch_bounds__(ND) void k_chunksum(
    const float* __restrict__ u,
    const float* __restrict__ log_A_real, const float* __restrict__ A_imag,
    const float* __restrict__ Bp, const float* __restrict__ log_dt,
    const float* __restrict__ Cp)
{
    int h = blockIdx.x, c = blockIdx.y, n = threadIdx.x;
    SSMParams P = make_params(log_A_real, A_imag, Bp, log_dt, Cp, h, n);

    float S0r = 0.f, S0i = 0.f, S1r = 0.f, S1i = 0.f;
    int t0 = c * CHUNK;
    #pragma unroll 4
    for (int k = 0; k < CHUNK; ++k) {
        int t = t0 + k;
        float q1, q2, vr, vi;
        step_qv(P, t, q1, q2, vr, vi);
        float u0 = u[t * NH + h];
        float u1 = u[LSEQ * NH + t * NH + h];
        S0r += u0 * q1;  S0i += u0 * q2;
        S1r += u1 * q1;  S1i += u1 * q2;
    }
    g_P[((0 * NH + h) * NCHUNK + c) * ND + n] = make_float2(S0r, S0i);
    g_P[((1 * NH + h) * NCHUNK + c) * ND + n] = make_float2(S1r, S1i);
}

__global__ __launch_bounds__(ND) void k_final(
    const float* __restrict__ u,
    const float* __restrict__ log_A_real, const float* __restrict__ A_imag,
    const float* __restrict__ Bp, const float* __restrict__ log_dt,
    const float* __restrict__ Cp, const float* __restrict__ Dp,
    float* __restrict__ out)
{
    __shared__ float psh[BSZ][CHUNK][ND + 1];   // +1 pad: conflict-free row reads
    int h = blockIdx.x, c = blockIdx.y, n = threadIdx.x;
    SSMParams P = make_params(log_A_real, A_imag, Bp, log_dt, Cp, h, n);

    // Exclusive prefix over preceding chunks (g_P is 4 MB, L2-resident).
    float S0r = 0.f, S0i = 0.f, S1r = 0.f, S1i = 0.f;
    for (int cc = 0; cc < c; ++cc) {
        float2 v0 = g_P[((0 * NH + h) * NCHUNK + cc) * ND + n];
        float2 v1 = g_P[((1 * NH + h) * NCHUNK + cc) * ND + n];
        S0r += v0.x; S0i += v0.y;
        S1r += v1.x; S1i += v1.y;
    }

    int t0 = c * CHUNK;
    #pragma unroll 4
    for (int k = 0; k < CHUNK; ++k) {
        int t = t0 + k;
        float q1, q2, vr, vi;
        step_qv(P, t, q1, q2, vr, vi);
        float u0 = u[t * NH + h];
        float u1 = u[LSEQ * NH + t * NH + h];
        S0r += u0 * q1;  S0i += u0 * q2;
        S1r += u1 * q1;  S1i += u1 * q2;
        // w = v * C[n];  partial y = Re(S * w)
        float wr = vr * P.Cr - vi * P.Ci;
        float wi = vr * P.Ci + vi * P.Cr;
        psh[0][k][n] = S0r * wr - S0i * wi;
        psh[1][k][n] = S1r * wr - S1i * wi;
    }
    __syncthreads();

    // Reduction over n: thread j owns local timestep j.
    int t = t0 + n;
    float y0 = 0.f, y1 = 0.f;
    #pragma unroll
    for (int i = 0; i < ND; ++i) {
        y0 += psh[0][n][i];
        y1 += psh[1][n][i];
    }
    float d = Dp[h];
    out[t * NH + h]            = y0 + u[t * NH + h] * d;
    out[LSEQ * NH + t * NH + h] = y1 + u[LSEQ * NH + t * NH + h] * d;
}

extern "C" void kernel_launch(void* const* d_in, const int* in_sizes, int n_in,
                              void* d_out, int out_size)
{
    const float* u          = (const float*)d_in[0];
    const float* log_A_real = (const float*)d_in[1];
    const float* A_imag     = (const float*)d_in[2];
    const float* Bp         = (const float*)d_in[3];
    const float* log_dt     = (const float*)d_in[4];
    const float* Cp         = (const float*)d_in[5];
    const float* Dp         = (const float*)d_in[6];
    float* out              = (float*)d_out;

    dim3 grid(NH, NCHUNK);
    k_chunksum<<<grid, ND>>>(u, log_A_real, A_imag, Bp, log_dt, Cp);
    k_final<<<grid, ND>>>(u, log_A_real, A_imag, Bp, log_dt, Cp, Dp, out);
}

// round 2
// speedup vs baseline: 1.4807x; 1.4807x over previous
#include <cuda_runtime.h>

// S4D selective-scan (non-stateful, eps-regularized) for B=2, L=2048, H=128, N=64.
//   term[b,t,h,n] = u[b,t,h] * dB[h,n] / (exp(dA[h,n]*t) + 1e-12)
//   x = cumsum_t(term) * exp(dA*t);  y = Re(sum_n x*C[n]);  out = y + u*D
// exp(dA*t) recomputed directly per t (expf + sincosf on the same fp32-rounded
// arguments as the reference) — numerics are cancellation-sensitive, so all
// summation orders are kept identical to the R1 kernel (rel_err 6.0e-4).
// R2 change: k_final's n-reduction is staged in 16-timestep quarters
// (smem 33KB -> 8.8KB), lifting occupancy 17% -> ~53%; u is staged in smem.

#define BSZ     2
#define LSEQ    2048
#define NH      128
#define ND      64
#define CHUNK   64
#define NCHUNK  (LSEQ / CHUNK)
#define QT      16              // staging quarter
#define NQ      (CHUNK / QT)
#define EPSV    1e-12f

// scratch: per-(b,h,chunk,n) complex chunk sums. 2*128*32*64 float2 = 4 MB.
__device__ float2 g_P[BSZ * NH * NCHUNK * ND];

struct SSMParams {
    float dAr, dAi;   // dA = Lam * step
    float dBr, dBi;   // dB = Bc * (exp(dA)-1) / Lam
    float Cr, Ci;     // C[n]
};

__device__ __forceinline__ SSMParams make_params(
    const float* __restrict__ log_A_real, const float* __restrict__ A_imag,
    const float* __restrict__ Bp, const float* __restrict__ log_dt,
    const float* __restrict__ Cp, int h, int n)
{
    int hn = h * ND + n;
    float LamR = -expf(log_A_real[hn]);
    float LamI = A_imag[hn];
    float step = expf(log_dt[0]);
    float dAr = LamR * step;
    float dAi = LamI * step;
    float e = expf(dAr);
    float s, c;
    sincosf(dAi, &s, &c);
    float em1r = e * c - 1.0f;
    float em1i = e * s;
    float Br = Bp[hn * 2 + 0], Bi = Bp[hn * 2 + 1];
    float numr = Br * em1r - Bi * em1i;
    float numi = Br * em1i + Bi * em1r;
    float inv = 1.0f / (LamR * LamR + LamI * LamI);
    SSMParams p;
    p.dAr = dAr; p.dAi = dAi;
    p.dBr = (numr * LamR + numi * LamI) * inv;
    p.dBi = (numi * LamR - numr * LamI) * inv;
    p.Cr = Cp[n * 2 + 0];
    p.Ci = Cp[n * 2 + 1];
    return p;
}

// q = dB / (exp(dA*t) + eps), v = exp(dA*t). b-independent heavy part.
__device__ __forceinline__ void step_qv(const SSMParams& P, int t,
                                        float& q1, float& q2,
                                        float& vr, float& vi)
{
    float tf = (float)t;
    float e = expf(P.dAr * tf);
    float sn, cs;
    sincosf(P.dAi * tf, &sn, &cs);
    vr = e * cs;
    vi = e * sn;
    float dc = vr + EPSV;           // eps on real part only (matches reference)
    float dd = vi;
    float inv = 1.0f / (dc * dc + dd * dd);
    q1 = (P.dBr * dc + P.dBi * dd) * inv;
    q2 = (P.dBi * dc - P.dBr * dd) * inv;
}

__global__ __launch_bounds__(ND) void k_chunksum(
    const float* __restrict__ u,
    const float* __restrict__ log_A_real, const float* __restrict__ A_imag,
    const float* __restrict__ Bp, const float* __restrict__ log_dt,
    const float* __restrict__ Cp)
{
    __shared__ float ush[BSZ][CHUNK];
    int h = blockIdx.x, c = blockIdx.y, n = threadIdx.x;
    int t0 = c * CHUNK;
    ush[0][n] = u[(t0 + n) * NH + h];
    ush[1][n] = u[LSEQ * NH + (t0 + n) * NH + h];
    SSMParams P = make_params(log_A_real, A_imag, Bp, log_dt, Cp, h, n);
    __syncthreads();

    float S0r = 0.f, S0i = 0.f, S1r = 0.f, S1i = 0.f;
    #pragma unroll 4
    for (int k = 0; k < CHUNK; ++k) {
        float q1, q2, vr, vi;
        step_qv(P, t0 + k, q1, q2, vr, vi);
        float u0 = ush[0][k];
        float u1 = ush[1][k];
        S0r += u0 * q1;  S0i += u0 * q2;
        S1r += u1 * q1;  S1i += u1 * q2;
    }
    g_P[((0 * NH + h) * NCHUNK + c) * ND + n] = make_float2(S0r, S0i);
    g_P[((1 * NH + h) * NCHUNK + c) * ND + n] = make_float2(S1r, S1i);
}

__global__ __launch_bounds__(ND) void k_final(
    const float* __restrict__ u,
    const float* __restrict__ log_A_real, const float* __restrict__ A_imag,
    const float* __restrict__ Bp, const float* __restrict__ log_dt,
    const float* __restrict__ Cp, const float* __restrict__ Dp,
    float* __restrict__ out)
{
    __shared__ float psh[BSZ][QT][ND + 1];   // 8.3 KB staging quarter
    __shared__ float ush[BSZ][CHUNK];
    int h = blockIdx.x, c = blockIdx.y, n = threadIdx.x;
    int t0 = c * CHUNK;
    ush[0][n] = u[(t0 + n) * NH + h];
    ush[1][n] = u[LSEQ * NH + (t0 + n) * NH + h];
    SSMParams P = make_params(log_A_real, A_imag, Bp, log_dt, Cp, h, n);
    float dD = Dp[h];

    // Exclusive prefix over preceding chunks (g_P is 4 MB, L2-resident).
    float S0r = 0.f, S0i = 0.f, S1r = 0.f, S1i = 0.f;
    for (int cc = 0; cc < c; ++cc) {
        float2 v0 = g_P[((0 * NH + h) * NCHUNK + cc) * ND + n];
        float2 v1 = g_P[((1 * NH + h) * NCHUNK + cc) * ND + n];
        S0r += v0.x; S0i += v0.y;
        S1r += v1.x; S1i += v1.y;
    }
    __syncthreads();   // ush ready

    for (int qrt = 0; qrt < NQ; ++qrt) {
        #pragma unroll
        for (int k = 0; k < QT; ++k) {
            int kk = qrt * QT + k;
            float q1, q2, vr, vi;
            step_qv(P, t0 + kk, q1, q2, vr, vi);
            float u0 = ush[0][kk];
            float u1 = ush[1][kk];
            S0r += u0 * q1;  S0i += u0 * q2;
            S1r += u1 * q1;  S1i += u1 * q2;
            // w = v * C[n];  partial y = Re(S * w)
            float wr = vr * P.Cr - vi * P.Ci;
            float wi = vr * P.Ci + vi * P.Cr;
            psh[0][k][n] = S0r * wr - S0i * wi;
            psh[1][k][n] = S1r * wr - S1i * wi;
        }
        __syncthreads();
        if (n < 2 * QT) {
            int b = n >> 4;            // 0..1
            int j = n & (QT - 1);      // local timestep in quarter
            int kk = qrt * QT + j;
            int t = t0 + kk;
            float y = 0.f;
            #pragma unroll
            for (int i = 0; i < ND; ++i)   // sequential: same order as R1
                y += psh[b][j][i];
            out[b * LSEQ * NH + t * NH + h] = y + ush[b][kk] * dD;
        }
        __syncthreads();
    }
}

extern "C" void kernel_launch(void* const* d_in, const int* in_sizes, int n_in,
                              void* d_out, int out_size)
{
    const float* u          = (const float*)d_in[0];
    const float* log_A_real = (const float*)d_in[1];
    const float* A_imag     = (const float*)d_in[2];
    const float* Bp         = (const float*)d_in[3];
    const float* log_dt     = (const float*)d_in[4];
    const float* Cp         = (const float*)d_in[5];
    const float* Dp         = (const float*)d_in[6];
    float* out              = (float*)d_out;

    dim3 grid(NH, NCHUNK);
    k_chunksum<<<grid, ND>>>(u, log_A_real, A_imag, Bp, log_dt, Cp);
    k_final<<<grid, ND>>>(u, log_A_real, A_imag, Bp, log_dt, Cp, Dp, out);
}